// round 5
// baseline (speedup 1.0000x reference)
#include <cuda_runtime.h>

// Fused Swin-window MHSA, fp32.
// One CTA = one (batch, window). 256 threads.
// Pipeline per head: stage W_h in smem -> Q,K,V gemms -> scores(+bias) ->
// softmax -> AV -> accumulate O-projection into registers. Final store once.

#define TPB     256
#define DDIM    128      // per-head dim == model dim
#define HEADS   8
#define WINSZ   7
#define PTOK    49       // tokens per window
#define JPAD    64       // padded token dim
#define CW      112      // patch-grid width (448/4)
#define NPATCH  12544    // tokens per image
#define NWIN    256      // windows per image (16x16)

struct SmemLayout {
    float xs[DDIM * JPAD];      // x window, d-major, cols 49..63 zeroed
    float qs[DDIM * JPAD];      // q (later reused as attention-output oh)
    float ks[DDIM * JPAD];      // k
    float vt[PTOK * DDIM];      // v, token-major (transposed)
    float ws[64 * 64];          // attention scores / weights
    float As[DDIM * DDIM];      // staged weight block [row][k]
    float bias[176];            // per-head relative position bias (169 used)
    int   pidx[64];             // window token -> patch index
    unsigned char rel[64 * 64]; // relative-index table
};

__device__ __forceinline__ void copy_contig(float* dst, const float* __restrict__ src, int tid) {
    float4* d4 = reinterpret_cast<float4*>(dst);
    const float4* s4 = reinterpret_cast<const float4*>(src);
    #pragma unroll
    for (int it = 0; it < 16; ++it)
        d4[tid + it * TPB] = s4[tid + it * TPB];
}

__device__ __forceinline__ void copy_wo(float* dst, const float* __restrict__ Wo, int hh, int tid) {
    float4* d4 = reinterpret_cast<float4*>(dst);
    #pragma unroll
    for (int it = 0; it < 16; ++it) {
        int f4 = tid + it * TPB;
        int r  = f4 >> 5;        // 32 float4 per 128-float row
        int k4 = f4 & 31;
        d4[f4] = *reinterpret_cast<const float4*>(Wo + r * 1024 + hh * 128 + k4 * 4);
    }
}

// acc[4][8] += A[128x128 row-major] @ B[128xJPAD], rows r0..r0+3, cols j0..j0+7
__device__ __forceinline__ void gemm128(const float* __restrict__ A, const float* __restrict__ B,
                                        int r0, int j0, float acc[4][8]) {
    #pragma unroll 4
    for (int k = 0; k < 128; ++k) {
        float4 b0 = *reinterpret_cast<const float4*>(&B[k * JPAD + j0]);
        float4 b1 = *reinterpret_cast<const float4*>(&B[k * JPAD + j0 + 4]);
        float bb[8] = {b0.x, b0.y, b0.z, b0.w, b1.x, b1.y, b1.z, b1.w};
        float aa[4];
        #pragma unroll
        for (int rr = 0; rr < 4; ++rr) aa[rr] = A[(r0 + rr) * 128 + k];
        #pragma unroll
        for (int rr = 0; rr < 4; ++rr)
            #pragma unroll
            for (int cc = 0; cc < 8; ++cc)
                acc[rr][cc] = fmaf(aa[rr], bb[cc], acc[rr][cc]);
    }
}

__global__ __launch_bounds__(TPB, 1)
void win_msa_kernel(const float* __restrict__ x,
                    const float* __restrict__ Wq, const float* __restrict__ bq,
                    const float* __restrict__ Wk, const float* __restrict__ bk,
                    const float* __restrict__ Wv, const float* __restrict__ bv,
                    const float* __restrict__ Wo, const float* __restrict__ bo,
                    const float* __restrict__ pos,
                    float* __restrict__ out) {
    extern __shared__ float smem_raw[];
    SmemLayout& sm = *reinterpret_cast<SmemLayout*>(smem_raw);

    const int tid = threadIdx.x;
    const int blk = blockIdx.x;
    const int n  = blk >> 8;            // image
    const int w  = blk & 255;           // window
    const int wy = w >> 4, wx = w & 15;

    const int cg = tid & 7;             // col group (8 cols each)
    const int rg = tid >> 3;            // row group (4 rows each)
    const int r0 = rg * 4;
    const int j0 = cg * 8;

    // ---- static tables ----
    if (tid < 64) {
        int j  = tid;
        int pr = j / 7, pc = j % 7;
        sm.pidx[j] = (j < PTOK) ? ((wy * 7 + pr) * CW + wx * 7 + pc) : 0;
    }
    for (int f = tid; f < 64 * 64; f += TPB) {
        int i = f >> 6, j = f & 63;
        int v = 0;
        if (i < PTOK && j < PTOK) {
            int ri = i / 7, ci = i % 7, rj = j / 7, cj = j % 7;
            v = (ri - rj + 6) + (ci - cj + 6) * 13;
        }
        sm.rel[f] = (unsigned char)v;
    }
    __syncthreads();

    // ---- load x window (zero the padding columns) ----
    const float* xb = x + (size_t)n * DDIM * NPATCH;
    for (int f = tid; f < DDIM * JPAD; f += TPB) {
        int d = f >> 6, j = f & 63;
        sm.xs[f] = (j < PTOK) ? xb[d * NPATCH + sm.pidx[j]] : 0.f;
    }

    // ---- persistent output accumulator (init with bo) ----
    float oacc[4][8];
    #pragma unroll
    for (int rr = 0; rr < 4; ++rr) {
        float b = bo[r0 + rr];
        #pragma unroll
        for (int cc = 0; cc < 8; ++cc) oacc[rr][cc] = b;
    }

    const float scale = 0.088388347648318447f;  // 1/sqrt(128)

    for (int hh = 0; hh < HEADS; ++hh) {
        __syncthreads();  // protect As/qs(oh)/bias from previous iteration readers
        if (tid < 169) sm.bias[tid] = pos[tid * HEADS + hh];

        // ---- Q ----
        copy_contig(sm.As, Wq + hh * 128 * 128, tid);
        __syncthreads();
        {
            float acc[4][8] = {};
            gemm128(sm.As, sm.xs, r0, j0, acc);
            #pragma unroll
            for (int rr = 0; rr < 4; ++rr) {
                float b = bq[hh * 128 + r0 + rr];
                #pragma unroll
                for (int cc = 0; cc < 8; ++cc)
                    sm.qs[(r0 + rr) * JPAD + j0 + cc] = acc[rr][cc] + b;
            }
        }
        __syncthreads();

        // ---- K ----
        copy_contig(sm.As, Wk + hh * 128 * 128, tid);
        __syncthreads();
        {
            float acc[4][8] = {};
            gemm128(sm.As, sm.xs, r0, j0, acc);
            #pragma unroll
            for (int rr = 0; rr < 4; ++rr) {
                float b = bk[hh * 128 + r0 + rr];
                #pragma unroll
                for (int cc = 0; cc < 8; ++cc)
                    sm.ks[(r0 + rr) * JPAD + j0 + cc] = acc[rr][cc] + b;
            }
        }
        __syncthreads();

        // ---- V (stored transposed: token-major) ----
        copy_contig(sm.As, Wv + hh * 128 * 128, tid);
        __syncthreads();
        {
            float acc[4][8] = {};
            gemm128(sm.As, sm.xs, r0, j0, acc);
            #pragma unroll
            for (int cc = 0; cc < 8; ++cc) {
                int tok = j0 + cc;
                if (tok < PTOK) {
                    #pragma unroll
                    for (int rr = 0; rr < 4; ++rr)
                        sm.vt[tok * DDIM + r0 + rr] = acc[rr][cc] + bv[hh * 128 + r0 + rr];
                }
            }
        }
        __syncthreads();

        // ---- scores: S[i,j] = sum_d k[d,i] * q[d,j], 2x8 tile per thread ----
        {
            const int i0 = (tid >> 3) * 2;  // 0..62
            float acc[2][8] = {};
            #pragma unroll 4
            for (int d = 0; d < 128; ++d) {
                float a0 = sm.ks[d * JPAD + i0];
                float a1 = sm.ks[d * JPAD + i0 + 1];
                float4 b0 = *reinterpret_cast<const float4*>(&sm.qs[d * JPAD + j0]);
                float4 b1 = *reinterpret_cast<const float4*>(&sm.qs[d * JPAD + j0 + 4]);
                float bb[8] = {b0.x, b0.y, b0.z, b0.w, b1.x, b1.y, b1.z, b1.w};
                #pragma unroll
                for (int cc = 0; cc < 8; ++cc) {
                    acc[0][cc] = fmaf(a0, bb[cc], acc[0][cc]);
                    acc[1][cc] = fmaf(a1, bb[cc], acc[1][cc]);
                }
            }
            #pragma unroll
            for (int ii = 0; ii < 2; ++ii)
                #pragma unroll
                for (int cc = 0; cc < 8; ++cc) {
                    int i = i0 + ii, j = j0 + cc;
                    sm.ws[i * 64 + j] = acc[ii][cc] * scale + sm.bias[sm.rel[i * 64 + j]];
                }
        }
        __syncthreads();

        // ---- softmax over key index i (one thread per query column j) ----
        if (tid < PTOK) {
            const int j = tid;
            float m = sm.ws[j];
            for (int i = 1; i < PTOK; ++i) m = fmaxf(m, sm.ws[i * 64 + j]);
            float s = 0.f;
            for (int i = 0; i < PTOK; ++i) {
                float e = __expf(sm.ws[i * 64 + j] - m);
                sm.ws[i * 64 + j] = e;
                s += e;
            }
            float r = 1.f / s;
            for (int i = 0; i < PTOK; ++i) sm.ws[i * 64 + j] *= r;
        }
        __syncthreads();

        // ---- AV: oh[d,j] = sum_i v[d,i] * w[i,j]  (oh stored into qs buffer) ----
        {
            float acc[4][8] = {};
            #pragma unroll 7
            for (int i = 0; i < PTOK; ++i) {
                float4 a = *reinterpret_cast<const float4*>(&sm.vt[i * DDIM + r0]);
                float4 b0 = *reinterpret_cast<const float4*>(&sm.ws[i * 64 + j0]);
                float4 b1 = *reinterpret_cast<const float4*>(&sm.ws[i * 64 + j0 + 4]);
                float aa[4] = {a.x, a.y, a.z, a.w};
                float bb[8] = {b0.x, b0.y, b0.z, b0.w, b1.x, b1.y, b1.z, b1.w};
                #pragma unroll
                for (int rr = 0; rr < 4; ++rr)
                    #pragma unroll
                    for (int cc = 0; cc < 8; ++cc)
                        acc[rr][cc] = fmaf(aa[rr], bb[cc], acc[rr][cc]);
            }
            #pragma unroll
            for (int rr = 0; rr < 4; ++rr)
                #pragma unroll
                for (int cc = 0; cc < 8; ++cc)
                    sm.qs[(r0 + rr) * JPAD + j0 + cc] = acc[rr][cc];
        }
        __syncthreads();

        // ---- O projection: oacc += Wo[:, hh*128:+128] @ oh ----
        copy_wo(sm.As, Wo, hh, tid);
        __syncthreads();
        gemm128(sm.As, sm.qs, r0, j0, oacc);
        // loop-top __syncthreads() protects As/qs before next head overwrites
    }

    // ---- final store ----
    float* ob = out + (size_t)n * DDIM * NPATCH;
    #pragma unroll
    for (int cc = 0; cc < 8; ++cc) {
        int j = j0 + cc;
        if (j < PTOK) {
            int p = sm.pidx[j];
            #pragma unroll
            for (int rr = 0; rr < 4; ++rr)
                ob[(size_t)(r0 + rr) * NPATCH + p] = oacc[rr][cc];
        }
    }
}

extern "C" void kernel_launch(void* const* d_in, const int* in_sizes, int n_in,
                              void* d_out, int out_size) {
    (void)in_sizes; (void)n_in; (void)out_size;
    const float* x   = (const float*)d_in[0];
    const float* Wq  = (const float*)d_in[1];
    const float* bq  = (const float*)d_in[2];
    const float* Wk  = (const float*)d_in[3];
    const float* bk  = (const float*)d_in[4];
    const float* Wv  = (const float*)d_in[5];
    const float* bv  = (const float*)d_in[6];
    const float* Wo  = (const float*)d_in[7];
    const float* bo  = (const float*)d_in[8];
    const float* pos = (const float*)d_in[9];
    float* out = (float*)d_out;

    const int smem_bytes = (int)sizeof(SmemLayout);
    cudaFuncSetAttribute(win_msa_kernel,
                         cudaFuncAttributeMaxDynamicSharedMemorySize, smem_bytes);

    // 4 images * 256 windows = 1024 CTAs
    win_msa_kernel<<<1024, TPB, smem_bytes>>>(x, Wq, bq, Wk, bk, Wv, bv, Wo, bo, pos, out);
}

// round 7
// speedup vs baseline: 1.0009x; 1.0009x over previous
#include <cuda_runtime.h>

// Fused Swin-window MHSA, fp32.
// One CTA = one (batch, window). 256 threads.
// Pipeline per head: stage W_h in smem -> Q,K,V gemms -> scores(+bias) ->
// softmax -> AV -> accumulate O-projection into registers. Final store once.

#define TPB     256
#define DDIM    128      // per-head dim == model dim
#define HEADS   8
#define WINSZ   7
#define PTOK    49       // tokens per window
#define JPAD    64       // padded token dim
#define CW      112      // patch-grid width (448/4)
#define NPATCH  12544    // tokens per image
#define NWIN    256      // windows per image (16x16)

struct SmemLayout {
    float xs[DDIM * JPAD];      // x window, d-major, cols 49..63 zeroed
    float qs[DDIM * JPAD];      // q (later reused as attention-output oh)
    float ks[DDIM * JPAD];      // k
    float vt[PTOK * DDIM];      // v, token-major (transposed)
    float ws[64 * 64];          // attention scores / weights
    float As[DDIM * DDIM];      // staged weight block [row][k]
    float bias[176];            // per-head relative position bias (169 used)
    int   pidx[64];             // window token -> patch index
    unsigned char rel[64 * 64]; // relative-index table
};

__device__ __forceinline__ void copy_contig(float* dst, const float* __restrict__ src, int tid) {
    float4* d4 = reinterpret_cast<float4*>(dst);
    const float4* s4 = reinterpret_cast<const float4*>(src);
    #pragma unroll
    for (int it = 0; it < 16; ++it)
        d4[tid + it * TPB] = s4[tid + it * TPB];
}

__device__ __forceinline__ void copy_wo(float* dst, const float* __restrict__ Wo, int hh, int tid) {
    float4* d4 = reinterpret_cast<float4*>(dst);
    #pragma unroll
    for (int it = 0; it < 16; ++it) {
        int f4 = tid + it * TPB;
        int r  = f4 >> 5;        // 32 float4 per 128-float row
        int k4 = f4 & 31;
        d4[f4] = *reinterpret_cast<const float4*>(Wo + r * 1024 + hh * 128 + k4 * 4);
    }
}

// acc[4][8] += A[128x128 row-major] @ B[128xJPAD], rows r0..r0+3, cols j0..j0+7
__device__ __forceinline__ void gemm128(const float* __restrict__ A, const float* __restrict__ B,
                                        int r0, int j0, float acc[4][8]) {
    #pragma unroll 4
    for (int k = 0; k < 128; ++k) {
        float4 b0 = *reinterpret_cast<const float4*>(&B[k * JPAD + j0]);
        float4 b1 = *reinterpret_cast<const float4*>(&B[k * JPAD + j0 + 4]);
        float bb[8] = {b0.x, b0.y, b0.z, b0.w, b1.x, b1.y, b1.z, b1.w};
        float aa[4];
        #pragma unroll
        for (int rr = 0; rr < 4; ++rr) aa[rr] = A[(r0 + rr) * 128 + k];
        #pragma unroll
        for (int rr = 0; rr < 4; ++rr)
            #pragma unroll
            for (int cc = 0; cc < 8; ++cc)
                acc[rr][cc] = fmaf(aa[rr], bb[cc], acc[rr][cc]);
    }
}

__global__ __launch_bounds__(TPB, 1)
void win_msa_kernel(const float* __restrict__ x,
                    const float* __restrict__ Wq, const float* __restrict__ bq,
                    const float* __restrict__ Wk, const float* __restrict__ bk,
                    const float* __restrict__ Wv, const float* __restrict__ bv,
                    const float* __restrict__ Wo, const float* __restrict__ bo,
                    const float* __restrict__ pos,
                    float* __restrict__ out) {
    extern __shared__ float smem_raw[];
    SmemLayout& sm = *reinterpret_cast<SmemLayout*>(smem_raw);

    const int tid = threadIdx.x;
    const int blk = blockIdx.x;
    const int n  = blk >> 8;            // image
    const int w  = blk & 255;           // window
    const int wy = w >> 4, wx = w & 15;

    const int cg = tid & 7;             // col group (8 cols each)
    const int rg = tid >> 3;            // row group (4 rows each)
    const int r0 = rg * 4;
    const int j0 = cg * 8;

    // ---- static tables ----
    if (tid < 64) {
        int j  = tid;
        int pr = j / 7, pc = j % 7;
        sm.pidx[j] = (j < PTOK) ? ((wy * 7 + pr) * CW + wx * 7 + pc) : 0;
    }
    for (int f = tid; f < 64 * 64; f += TPB) {
        int i = f >> 6, j = f & 63;
        int v = 0;
        if (i < PTOK && j < PTOK) {
            int ri = i / 7, ci = i % 7, rj = j / 7, cj = j % 7;
            v = (ri - rj + 6) + (ci - cj + 6) * 13;
        }
        sm.rel[f] = (unsigned char)v;
    }
    __syncthreads();

    // ---- load x window (zero the padding columns) ----
    const float* xb = x + (size_t)n * DDIM * NPATCH;
    for (int f = tid; f < DDIM * JPAD; f += TPB) {
        int d = f >> 6, j = f & 63;
        sm.xs[f] = (j < PTOK) ? xb[d * NPATCH + sm.pidx[j]] : 0.f;
    }

    // ---- persistent output accumulator (init with bo) ----
    float oacc[4][8];
    #pragma unroll
    for (int rr = 0; rr < 4; ++rr) {
        float b = bo[r0 + rr];
        #pragma unroll
        for (int cc = 0; cc < 8; ++cc) oacc[rr][cc] = b;
    }

    const float scale = 0.088388347648318447f;  // 1/sqrt(128)

    for (int hh = 0; hh < HEADS; ++hh) {
        __syncthreads();  // protect As/qs(oh)/bias from previous iteration readers
        if (tid < 169) sm.bias[tid] = pos[tid * HEADS + hh];

        // ---- Q ----
        copy_contig(sm.As, Wq + hh * 128 * 128, tid);
        __syncthreads();
        {
            float acc[4][8] = {};
            gemm128(sm.As, sm.xs, r0, j0, acc);
            #pragma unroll
            for (int rr = 0; rr < 4; ++rr) {
                float b = bq[hh * 128 + r0 + rr];
                #pragma unroll
                for (int cc = 0; cc < 8; ++cc)
                    sm.qs[(r0 + rr) * JPAD + j0 + cc] = acc[rr][cc] + b;
            }
        }
        __syncthreads();

        // ---- K ----
        copy_contig(sm.As, Wk + hh * 128 * 128, tid);
        __syncthreads();
        {
            float acc[4][8] = {};
            gemm128(sm.As, sm.xs, r0, j0, acc);
            #pragma unroll
            for (int rr = 0; rr < 4; ++rr) {
                float b = bk[hh * 128 + r0 + rr];
                #pragma unroll
                for (int cc = 0; cc < 8; ++cc)
                    sm.ks[(r0 + rr) * JPAD + j0 + cc] = acc[rr][cc] + b;
            }
        }
        __syncthreads();

        // ---- V (stored transposed: token-major) ----
        copy_contig(sm.As, Wv + hh * 128 * 128, tid);
        __syncthreads();
        {
            float acc[4][8] = {};
            gemm128(sm.As, sm.xs, r0, j0, acc);
            #pragma unroll
            for (int cc = 0; cc < 8; ++cc) {
                int tok = j0 + cc;
                if (tok < PTOK) {
                    #pragma unroll
                    for (int rr = 0; rr < 4; ++rr)
                        sm.vt[tok * DDIM + r0 + rr] = acc[rr][cc] + bv[hh * 128 + r0 + rr];
                }
            }
        }
        __syncthreads();

        // ---- scores: S[i,j] = sum_d k[d,i] * q[d,j], 2x8 tile per thread ----
        {
            const int i0 = (tid >> 3) * 2;  // 0..62
            float acc[2][8] = {};
            #pragma unroll 4
            for (int d = 0; d < 128; ++d) {
                float a0 = sm.ks[d * JPAD + i0];
                float a1 = sm.ks[d * JPAD + i0 + 1];
                float4 b0 = *reinterpret_cast<const float4*>(&sm.qs[d * JPAD + j0]);
                float4 b1 = *reinterpret_cast<const float4*>(&sm.qs[d * JPAD + j0 + 4]);
                float bb[8] = {b0.x, b0.y, b0.z, b0.w, b1.x, b1.y, b1.z, b1.w};
                #pragma unroll
                for (int cc = 0; cc < 8; ++cc) {
                    acc[0][cc] = fmaf(a0, bb[cc], acc[0][cc]);
                    acc[1][cc] = fmaf(a1, bb[cc], acc[1][cc]);
                }
            }
            #pragma unroll
            for (int ii = 0; ii < 2; ++ii)
                #pragma unroll
                for (int cc = 0; cc < 8; ++cc) {
                    int i = i0 + ii, j = j0 + cc;
                    sm.ws[i * 64 + j] = acc[ii][cc] * scale + sm.bias[sm.rel[i * 64 + j]];
                }
        }
        __syncthreads();

        // ---- softmax over key index i (one thread per query column j) ----
        if (tid < PTOK) {
            const int j = tid;
            float m = sm.ws[j];
            for (int i = 1; i < PTOK; ++i) m = fmaxf(m, sm.ws[i * 64 + j]);
            float s = 0.f;
            for (int i = 0; i < PTOK; ++i) {
                float e = __expf(sm.ws[i * 64 + j] - m);
                sm.ws[i * 64 + j] = e;
                s += e;
            }
            float r = 1.f / s;
            for (int i = 0; i < PTOK; ++i) sm.ws[i * 64 + j] *= r;
        }
        __syncthreads();

        // ---- AV: oh[d,j] = sum_i v[d,i] * w[i,j]  (oh stored into qs buffer) ----
        {
            float acc[4][8] = {};
            #pragma unroll 7
            for (int i = 0; i < PTOK; ++i) {
                float4 a = *reinterpret_cast<const float4*>(&sm.vt[i * DDIM + r0]);
                float4 b0 = *reinterpret_cast<const float4*>(&sm.ws[i * 64 + j0]);
                float4 b1 = *reinterpret_cast<const float4*>(&sm.ws[i * 64 + j0 + 4]);
                float aa[4] = {a.x, a.y, a.z, a.w};
                float bb[8] = {b0.x, b0.y, b0.z, b0.w, b1.x, b1.y, b1.z, b1.w};
                #pragma unroll
                for (int rr = 0; rr < 4; ++rr)
                    #pragma unroll
                    for (int cc = 0; cc < 8; ++cc)
                        acc[rr][cc] = fmaf(aa[rr], bb[cc], acc[rr][cc]);
            }
            #pragma unroll
            for (int rr = 0; rr < 4; ++rr)
                #pragma unroll
                for (int cc = 0; cc < 8; ++cc)
                    sm.qs[(r0 + rr) * JPAD + j0 + cc] = acc[rr][cc];
        }
        __syncthreads();

        // ---- O projection: oacc += Wo[:, hh*128:+128] @ oh ----
        copy_wo(sm.As, Wo, hh, tid);
        __syncthreads();
        gemm128(sm.As, sm.qs, r0, j0, oacc);
        // loop-top __syncthreads() protects As/qs before next head overwrites
    }

    // ---- final store ----
    float* ob = out + (size_t)n * DDIM * NPATCH;
    #pragma unroll
    for (int cc = 0; cc < 8; ++cc) {
        int j = j0 + cc;
        if (j < PTOK) {
            int p = sm.pidx[j];
            #pragma unroll
            for (int rr = 0; rr < 4; ++rr)
                ob[(size_t)(r0 + rr) * NPATCH + p] = oacc[rr][cc];
        }
    }
}

extern "C" void kernel_launch(void* const* d_in, const int* in_sizes, int n_in,
                              void* d_out, int out_size) {
    (void)in_sizes; (void)n_in; (void)out_size;
    const float* x   = (const float*)d_in[0];
    const float* Wq  = (const float*)d_in[1];
    const float* bq  = (const float*)d_in[2];
    const float* Wk  = (const float*)d_in[3];
    const float* bk  = (const float*)d_in[4];
    const float* Wv  = (const float*)d_in[5];
    const float* bv  = (const float*)d_in[6];
    const float* Wo  = (const float*)d_in[7];
    const float* bo  = (const float*)d_in[8];
    const float* pos = (const float*)d_in[9];
    float* out = (float*)d_out;

    const int smem_bytes = (int)sizeof(SmemLayout);
    cudaFuncSetAttribute(win_msa_kernel,
                         cudaFuncAttributeMaxDynamicSharedMemorySize, smem_bytes);

    // 4 images * 256 windows = 1024 CTAs
    win_msa_kernel<<<1024, TPB, smem_bytes>>>(x, Wq, bq, Wk, bk, Wv, bv, Wo, bo, pos, out);
}

// round 8
// speedup vs baseline: 3.1241x; 3.1214x over previous
#include <cuda_runtime.h>
#include <cuda_bf16.h>
#include <cstdint>

#define TPB    256
#define NPATCH 12544
#define CW     112
#define LDX    136                  // row stride (bf16) for [64][128] buffers: 272B == 16 mod 128
#define LDV    72                   // row stride for [*][64] buffers: 144B == 16 mod 128
#define LDF    68                   // fp32 score row stride
#define PSX    (64 * LDX)           // plane stride (hi->lo) in elements
#define PSV    (128 * LDV)
#define PSW    (64 * LDV)
#define PSS    (128 * LDV)

struct __align__(16) Smem {
    __nv_bfloat16 xT[2 * PSX];      // x^T  [tok][d], hi/lo planes
    __nv_bfloat16 qT[2 * PSX];      // q^T (scaled); later oh^T
    __nv_bfloat16 kT[2 * PSX];      // k^T; fp32 scores aliased on top after S gemm
    __nv_bfloat16 v [2 * PSV];      // v    [d][tok]
    __nv_bfloat16 wT[2 * PSW];      // softmax weights^T [j][i]
    __nv_bfloat16 ws[2 * PSS];      // weight stage [row][k-half]
    float         bias[172];
    int           pidx[64];
    unsigned char rel[4096];
};

__device__ __forceinline__ void ldm4(uint32_t r[4], uint32_t a) {
    asm volatile("ldmatrix.sync.aligned.m8n8.x4.shared.b16 {%0,%1,%2,%3},[%4];\n"
        : "=r"(r[0]), "=r"(r[1]), "=r"(r[2]), "=r"(r[3]) : "r"(a));
}

__device__ __forceinline__ void mma_bf16(float c[4], const uint32_t a[4],
                                         uint32_t b0, uint32_t b1) {
    asm volatile("mma.sync.aligned.m16n8k16.row.col.f32.bf16.bf16.f32 "
        "{%0,%1,%2,%3},{%4,%5,%6,%7},{%8,%9},{%0,%1,%2,%3};\n"
        : "+f"(c[0]), "+f"(c[1]), "+f"(c[2]), "+f"(c[3])
        : "r"(a[0]), "r"(a[1]), "r"(a[2]), "r"(a[3]), "r"(b0), "r"(b1));
}

__device__ __forceinline__ void sstore(__nv_bfloat16* p, int ps, float v) {
    __nv_bfloat16 h = __float2bfloat16(v);
    p[0]  = h;
    p[ps] = __float2bfloat16(v - __bfloat162float(h));
}

// store two adjacent columns (4B-aligned) as bf16x2 pairs, hi and lo planes
__device__ __forceinline__ void sstore2(__nv_bfloat16* p, int ps, float v0, float v1) {
    __nv_bfloat16 h0 = __float2bfloat16(v0);
    __nv_bfloat16 h1 = __float2bfloat16(v1);
    *reinterpret_cast<__nv_bfloat162*>(p) = __halves2bfloat162(h0, h1);
    __nv_bfloat16 l0 = __float2bfloat16(v0 - __bfloat162float(h0));
    __nv_bfloat16 l1 = __float2bfloat16(v1 - __bfloat162float(h1));
    *reinterpret_cast<__nv_bfloat162*>(p + ps) = __halves2bfloat162(l0, l1);
}

// C[m0..m0+15][n0..n0+NT*8) += A(hi+lo) * B(hi+lo)^T  (error-compensated, 3 mma)
// A0 = &A[m0][k0] row-major [M][K]; B0 = &BT[n0][k0] row-major [N][K].
template<int NT, int KC>
__device__ __forceinline__ void wgemm(const __nv_bfloat16* A0, int ldA, int psA,
                                      const __nv_bfloat16* B0, int ldB, int psB,
                                      float (*c)[4], int lane) {
    const int arow = lane & 15, acol = (lane >> 4) * 8;
    const int bsub = (lane & 7) + ((lane & 16) >> 1), bcol = lane & 8;
    uint32_t aU = (uint32_t)__cvta_generic_to_shared(A0 + arow * ldA + acol);
    uint32_t bU = (uint32_t)__cvta_generic_to_shared(B0 + bsub * ldB + bcol);
    const uint32_t psA2 = (uint32_t)psA * 2u, psB2 = (uint32_t)psB * 2u;
    #pragma unroll
    for (int kc = 0; kc < KC; ++kc) {
        uint32_t ah[4], al[4];
        ldm4(ah, aU);
        ldm4(al, aU + psA2);
        #pragma unroll
        for (int t = 0; t < NT / 2; ++t) {
            uint32_t bh[4], bl[4];
            uint32_t bp = bU + (uint32_t)(t * 16 * ldB * 2);
            ldm4(bh, bp);
            ldm4(bl, bp + psB2);
            mma_bf16(c[2 * t],     ah, bh[0], bh[1]);
            mma_bf16(c[2 * t],     ah, bl[0], bl[1]);
            mma_bf16(c[2 * t],     al, bh[0], bh[1]);
            mma_bf16(c[2 * t + 1], ah, bh[2], bh[3]);
            mma_bf16(c[2 * t + 1], ah, bl[2], bl[3]);
            mma_bf16(c[2 * t + 1], al, bh[2], bh[3]);
        }
        aU += 32;  // 16 bf16
        bU += 32;
    }
}

// stage 128 rows x 64 cols of an fp32 weight (cols kofs..kofs+63) into sm.ws hi/lo
__device__ __forceinline__ void stage_w(Smem& sm, const float* __restrict__ W,
                                        int rstride, int kofs, int tid) {
    #pragma unroll
    for (int it = 0; it < 8; ++it) {
        int f4 = tid + it * TPB;            // 0..2047, 16 float4 per row
        int r  = f4 >> 4, c4 = (f4 & 15) * 4;
        float4 u = *reinterpret_cast<const float4*>(W + r * rstride + kofs + c4);
        __nv_bfloat16* d = sm.ws + r * LDV + c4;
        sstore2(d,     PSS, u.x, u.y);
        sstore2(d + 2, PSS, u.z, u.w);
    }
}

__global__ __launch_bounds__(TPB, 1)
void win_msa_mma(const float* __restrict__ x,
                 const float* __restrict__ Wq, const float* __restrict__ bq,
                 const float* __restrict__ Wk, const float* __restrict__ bk,
                 const float* __restrict__ Wv, const float* __restrict__ bv,
                 const float* __restrict__ Wo, const float* __restrict__ bo,
                 const float* __restrict__ pos, float* __restrict__ out) {
    extern __shared__ char smraw[];
    Smem& sm = *reinterpret_cast<Smem*>(smraw);

    const int tid  = threadIdx.x, lane = tid & 31, w = tid >> 5;
    const int n    = blockIdx.x >> 8, win = blockIdx.x & 255;
    const int wy   = win >> 4, wx = win & 15;
    const int mq   = (w & 3) * 16;   // m0 for M=64 gemms (token rows)
    const int nq   = (w >> 2) * 64;  // n0 for N=128 gemms (8 n-tiles/warp)
    const int nS   = (w >> 2) * 32;  // n0 for score gemm (4 n-tiles/warp)
    const int mv   = w * 16;         // m0 for V gemm (d rows)
    const int g    = lane >> 2, tc = (lane & 3) * 2;
    const float scale = 0.088388347648318447f;  // 1/sqrt(128)

    if (tid < 64) {
        int pr = tid / 7, pc = tid % 7;
        sm.pidx[tid] = (tid < 49) ? ((wy * 7 + pr) * CW + wx * 7 + pc) : 0;
    }
    for (int f = tid; f < 4096; f += TPB) {
        int i = f >> 6, j = f & 63, vv = 0;
        if (i < 49 && j < 49)
            vv = (i / 7 - j / 7 + 6) + (i % 7 - j % 7 + 6) * 13;
        sm.rel[f] = (unsigned char)vv;
    }
    __syncthreads();

    // ---- load x window transposed: xT[tok][d], rows 49..63 zero ----
    const float* xb = x + (size_t)n * 128 * NPATCH;
    for (int f = tid; f < 8192; f += TPB) {
        int tok = f & 63, d = f >> 6;
        float vv = (tok < 49) ? xb[d * NPATCH + sm.pidx[tok]] : 0.f;
        sstore(sm.xT + tok * LDX + d, PSX, vv);
    }

    // ---- persistent O accumulator fragments (out^T[j][o]), init with bo ----
    float oacc[8][4];
    #pragma unroll
    for (int t = 0; t < 8; ++t) {
        int col = nq + t * 8 + tc;
        oacc[t][0] = bo[col];     oacc[t][1] = bo[col + 1];
        oacc[t][2] = bo[col];     oacc[t][3] = bo[col + 1];
    }

    for (int hh = 0; hh < 8; ++hh) {
        __syncthreads();                       // prev head fully done
        if (tid < 169) sm.bias[tid] = pos[tid * 8 + hh];

        // ================= Q^T = xT @ Wq^T  (M=64 tok, N=128 d, K=128) =====
        float cq[8][4];
        #pragma unroll
        for (int t = 0; t < 8; ++t) cq[t][0] = cq[t][1] = cq[t][2] = cq[t][3] = 0.f;
        #pragma unroll
        for (int kh = 0; kh < 2; ++kh) {
            stage_w(sm, Wq + hh * 16384, 128, kh * 64, tid);
            __syncthreads();
            wgemm<8, 4>(sm.xT + mq * LDX + kh * 64, LDX, PSX,
                        sm.ws + nq * LDV, LDV, PSS, cq, lane);
            __syncthreads();
        }
        {
            const float* bqh = bq + hh * 128;
            #pragma unroll
            for (int t = 0; t < 8; ++t) {
                int col = nq + t * 8 + tc, r0 = mq + g, r1 = r0 + 8;
                sstore2(sm.qT + r0 * LDX + col, PSX,
                        (cq[t][0] + bqh[col]) * scale, (cq[t][1] + bqh[col + 1]) * scale);
                sstore2(sm.qT + r1 * LDX + col, PSX,
                        (cq[t][2] + bqh[col]) * scale, (cq[t][3] + bqh[col + 1]) * scale);
            }
        }

        // ================= K^T = xT @ Wk^T ================================
        float ck[8][4];
        #pragma unroll
        for (int t = 0; t < 8; ++t) ck[t][0] = ck[t][1] = ck[t][2] = ck[t][3] = 0.f;
        #pragma unroll
        for (int kh = 0; kh < 2; ++kh) {
            stage_w(sm, Wk + hh * 16384, 128, kh * 64, tid);
            __syncthreads();
            wgemm<8, 4>(sm.xT + mq * LDX + kh * 64, LDX, PSX,
                        sm.ws + nq * LDV, LDV, PSS, ck, lane);
            __syncthreads();
        }
        {
            const float* bkh = bk + hh * 128;
            #pragma unroll
            for (int t = 0; t < 8; ++t) {
                int col = nq + t * 8 + tc, r0 = mq + g, r1 = r0 + 8;
                sstore2(sm.kT + r0 * LDX + col, PSX,
                        ck[t][0] + bkh[col], ck[t][1] + bkh[col + 1]);
                sstore2(sm.kT + r1 * LDX + col, PSX,
                        ck[t][2] + bkh[col], ck[t][3] + bkh[col + 1]);
            }
        }

        // ================= V = Wv @ x  (M=128 d, N=64 tok, K=128) ==========
        float cv[8][4];
        #pragma unroll
        for (int t = 0; t < 8; ++t) cv[t][0] = cv[t][1] = cv[t][2] = cv[t][3] = 0.f;
        #pragma unroll
        for (int kh = 0; kh < 2; ++kh) {
            stage_w(sm, Wv + hh * 16384, 128, kh * 64, tid);
            __syncthreads();
            wgemm<8, 4>(sm.ws + mv * LDV, LDV, PSS,
                        sm.xT + kh * 64, LDX, PSX, cv, lane);
            __syncthreads();
        }
        {
            const float* bvh = bv + hh * 128;
            #pragma unroll
            for (int t = 0; t < 8; ++t) {
                int tok = t * 8 + tc;
                int d0 = mv + g, d1 = d0 + 8;
                sstore2(sm.v + d0 * LDV + tok, PSV,
                        cv[t][0] + bvh[d0], cv[t][1] + bvh[d0]);
                sstore2(sm.v + d1 * LDV + tok, PSV,
                        cv[t][2] + bvh[d1], cv[t][3] + bvh[d1]);
            }
        }
        __syncthreads();   // qT, kT, v epilogues visible to all warps

        // ================= S^T[j][i] = qT @ kT^T (M=64, N=64, K=128) =======
        float cs[4][4];
        #pragma unroll
        for (int t = 0; t < 4; ++t) cs[t][0] = cs[t][1] = cs[t][2] = cs[t][3] = 0.f;
        wgemm<4, 8>(sm.qT + mq * LDX, LDX, PSX,
                    sm.kT + nS * LDX, LDX, PSX, cs, lane);
        __syncthreads();   // all reads of kT done before aliased score writes

        float* stf = reinterpret_cast<float*>(sm.kT);
        #pragma unroll
        for (int t = 0; t < 4; ++t) {
            int i = nS + t * 8 + tc, j0 = mq + g, j1 = j0 + 8;
            stf[j0 * LDF + i]     = cs[t][0] + sm.bias[sm.rel[(i << 6) + j0]];
            stf[j0 * LDF + i + 1] = cs[t][1] + sm.bias[sm.rel[((i + 1) << 6) + j0]];
            stf[j1 * LDF + i]     = cs[t][2] + sm.bias[sm.rel[(i << 6) + j1]];
            stf[j1 * LDF + i + 1] = cs[t][3] + sm.bias[sm.rel[((i + 1) << 6) + j1]];
        }
        __syncthreads();

        // ================= softmax over i, per row j; write wT hi/lo ========
        if (tid < 64) {
            int j = tid;
            float m = -1e30f;
            for (int i = 0; i < 49; ++i) m = fmaxf(m, stf[j * LDF + i]);
            float s = 0.f;
            for (int i = 0; i < 49; ++i) {
                float e = __expf(stf[j * LDF + i] - m);
                stf[j * LDF + i] = e;
                s += e;
            }
            float r = 1.f / s;
            for (int i = 0; i < 49; ++i)
                sstore(sm.wT + j * LDV + i, PSW, stf[j * LDF + i] * r);
            __nv_bfloat16 z = __float2bfloat16(0.f);
            for (int i = 49; i < 64; ++i) {
                sm.wT[j * LDV + i]       = z;
                sm.wT[j * LDV + i + PSW] = z;
            }
        }
        __syncthreads();

        // ================= oh^T = wT @ v^T (M=64 tok, N=128 d, K=64) =======
        float ca[8][4];
        #pragma unroll
        for (int t = 0; t < 8; ++t) ca[t][0] = ca[t][1] = ca[t][2] = ca[t][3] = 0.f;
        wgemm<8, 4>(sm.wT + mq * LDV, LDV, PSW,
                    sm.v + nq * LDV, LDV, PSV, ca, lane);
        {   // epilogue -> ohT (aliased over qT; safe: AV reads only wT/v)
            #pragma unroll
            for (int t = 0; t < 8; ++t) {
                int col = nq + t * 8 + tc, r0 = mq + g, r1 = r0 + 8;
                sstore2(sm.qT + r0 * LDX + col, PSX, ca[t][0], ca[t][1]);
                sstore2(sm.qT + r1 * LDX + col, PSX, ca[t][2], ca[t][3]);
            }
        }
        __syncthreads();

        // ================= out^T += ohT @ WoSlice^T (persistent oacc) ======
        #pragma unroll
        for (int kh = 0; kh < 2; ++kh) {
            stage_w(sm, Wo + hh * 128, 1024, kh * 64, tid);
            __syncthreads();
            wgemm<8, 4>(sm.qT + mq * LDX + kh * 64, LDX, PSX,
                        sm.ws + nq * LDV, LDV, PSS, oacc, lane);
            __syncthreads();
        }
    }

    // ---- final store: outT[j][o] -> out[n][o][patch] ----
    float* ob = out + (size_t)n * 128 * NPATCH;
    const int j0 = mq + g, j1 = j0 + 8;
    #pragma unroll
    for (int t = 0; t < 8; ++t) {
        int col = nq + t * 8 + tc;
        if (j0 < 49) {
            int p = sm.pidx[j0];
            ob[(size_t)col * NPATCH + p]       = oacc[t][0];
            ob[(size_t)(col + 1) * NPATCH + p] = oacc[t][1];
        }
        if (j1 < 49) {
            int p = sm.pidx[j1];
            ob[(size_t)col * NPATCH + p]       = oacc[t][2];
            ob[(size_t)(col + 1) * NPATCH + p] = oacc[t][3];
        }
    }
}

extern "C" void kernel_launch(void* const* d_in, const int* in_sizes, int n_in,
                              void* d_out, int out_size) {
    (void)in_sizes; (void)n_in; (void)out_size;
    const float* x   = (const float*)d_in[0];
    const float* Wq  = (const float*)d_in[1];
    const float* bq  = (const float*)d_in[2];
    const float* Wk  = (const float*)d_in[3];
    const float* bk  = (const float*)d_in[4];
    const float* Wv  = (const float*)d_in[5];
    const float* bv  = (const float*)d_in[6];
    const float* Wo  = (const float*)d_in[7];
    const float* bo  = (const float*)d_in[8];
    const float* pos = (const float*)d_in[9];
    float* out = (float*)d_out;

    const int smem_bytes = (int)sizeof(Smem);
    cudaFuncSetAttribute(win_msa_mma,
                         cudaFuncAttributeMaxDynamicSharedMemorySize, smem_bytes);
    win_msa_mma<<<1024, TPB, smem_bytes>>>(x, Wq, bq, Wk, bk, Wv, bv, Wo, bo, pos, out);
}

// round 11
// speedup vs baseline: 4.3446x; 1.3907x over previous
#include <cuda_runtime.h>
#include <cuda_bf16.h>
#include <cstdint>

#define TPB    256
#define NPATCH 12544
#define CW     112
#define LDX    136                  // row stride (bf16) for [64][128] buffers: 272B == 16 mod 128
#define LDV    72                   // row stride for [*][64] buffers: 144B == 16 mod 128
#define LDF    68                   // fp32 score row stride
#define PSX    (64 * LDX)           // plane stride (hi->lo) in elements
#define PSV    (128 * LDV)
#define PSW    (64 * LDV)
#define PSS    (128 * LDV)          // ws-image plane stride = 9216
#define STG_E  (2 * PSS)            // elems per weight stage image = 18432
#define STG_B  (STG_E * 2)          // bytes per stage = 36864

// Pre-split weight images: 64 stages (hh*8 + mat*2 + kh), each hi/lo planes
// of [128 rows][LDV] bf16 — byte-identical to the smem stage buffer.
__device__ __align__(16) __nv_bfloat16 g_wpk[64 * STG_E];

struct __align__(16) Smem {
    __nv_bfloat16 xT[2 * PSX];      // x^T  [tok][d], hi/lo planes
    __nv_bfloat16 qT[2 * PSX];      // q^T (scaled); later oh^T
    __nv_bfloat16 kT[2 * PSX];      // k^T; fp32 scores aliased on top after S gemm
    __nv_bfloat16 v [2 * PSV];      // v    [d][tok]
    __nv_bfloat16 ws[2 * STG_E];    // two weight stage buffers (b0, b1); wT aliases b1
    float         bias[172];
    int           pidx[64];
    unsigned char rel[4096];
};

__device__ __forceinline__ void ldm4(uint32_t r[4], uint32_t a) {
    asm volatile("ldmatrix.sync.aligned.m8n8.x4.shared.b16 {%0,%1,%2,%3},[%4];\n"
        : "=r"(r[0]), "=r"(r[1]), "=r"(r[2]), "=r"(r[3]) : "r"(a));
}

__device__ __forceinline__ void mma_bf16(float c[4], const uint32_t a[4],
                                         uint32_t b0, uint32_t b1) {
    asm volatile("mma.sync.aligned.m16n8k16.row.col.f32.bf16.bf16.f32 "
        "{%0,%1,%2,%3},{%4,%5,%6,%7},{%8,%9},{%0,%1,%2,%3};\n"
        : "+f"(c[0]), "+f"(c[1]), "+f"(c[2]), "+f"(c[3])
        : "r"(a[0]), "r"(a[1]), "r"(a[2]), "r"(a[3]), "r"(b0), "r"(b1));
}

__device__ __forceinline__ void sstore(__nv_bfloat16* p, int ps, float v) {
    __nv_bfloat16 h = __float2bfloat16(v);
    p[0]  = h;
    p[ps] = __float2bfloat16(v - __bfloat162float(h));
}

__device__ __forceinline__ void sstore2(__nv_bfloat16* p, int ps, float v0, float v1) {
    __nv_bfloat16 h0 = __float2bfloat16(v0);
    __nv_bfloat16 h1 = __float2bfloat16(v1);
    *reinterpret_cast<__nv_bfloat162*>(p) = __halves2bfloat162(h0, h1);
    __nv_bfloat16 l0 = __float2bfloat16(v0 - __bfloat162float(h0));
    __nv_bfloat16 l1 = __float2bfloat16(v1 - __bfloat162float(h1));
    *reinterpret_cast<__nv_bfloat162*>(p + ps) = __halves2bfloat162(l0, l1);
}

// C[m0..+16)[n0..n0+NT*8) += A(hi+lo) * B(hi+lo)^T, error-compensated (3 mma).
template<int NT, int KC>
__device__ __forceinline__ void wgemm(const __nv_bfloat16* A0, int ldA, int psA,
                                      const __nv_bfloat16* B0, int ldB, int psB,
                                      float (*c)[4], int lane) {
    const int arow = lane & 15, acol = (lane >> 4) * 8;
    const int bsub = (lane & 7) + ((lane & 16) >> 1), bcol = lane & 8;
    uint32_t aU = (uint32_t)__cvta_generic_to_shared(A0 + arow * ldA + acol);
    uint32_t bU = (uint32_t)__cvta_generic_to_shared(B0 + bsub * ldB + bcol);
    const uint32_t psA2 = (uint32_t)psA * 2u, psB2 = (uint32_t)psB * 2u;
    #pragma unroll
    for (int kc = 0; kc < KC; ++kc) {
        uint32_t ah[4], al[4];
        ldm4(ah, aU);
        ldm4(al, aU + psA2);
        #pragma unroll
        for (int t = 0; t < NT / 2; ++t) {
            uint32_t bh[4], bl[4];
            uint32_t bp = bU + (uint32_t)(t * 16 * ldB * 2);
            ldm4(bh, bp);
            ldm4(bl, bp + psB2);
            mma_bf16(c[2 * t],     ah, bh[0], bh[1]);
            mma_bf16(c[2 * t],     ah, bl[0], bl[1]);
            mma_bf16(c[2 * t],     al, bh[0], bh[1]);
            mma_bf16(c[2 * t + 1], ah, bh[2], bh[3]);
            mma_bf16(c[2 * t + 1], ah, bl[2], bl[3]);
            mma_bf16(c[2 * t + 1], al, bh[2], bh[3]);
        }
        aU += 32;  // 16 bf16
        bU += 32;
    }
}

// ---- async weight staging (pre-split image -> smem buffer) ----
__device__ __forceinline__ void prefetch_stage(__nv_bfloat16* buf, int stage, int tid) {
    const char* src = reinterpret_cast<const char*>(g_wpk) + (size_t)stage * STG_B;
    uint32_t dst = (uint32_t)__cvta_generic_to_shared(buf);
    #pragma unroll
    for (int it = 0; it < 9; ++it) {
        int o = (tid + it * TPB) * 16;
        asm volatile("cp.async.cg.shared.global [%0], [%1], 16;\n"
            :: "r"(dst + o), "l"(src + o));
    }
    asm volatile("cp.async.commit_group;\n");
}
#define CPWAIT1 asm volatile("cp.async.wait_group 1;\n" ::: "memory")
#define CPWAIT0 asm volatile("cp.async.wait_group 0;\n" ::: "memory")

// ---- pack kernel: split fp32 weights into hi/lo bf16 stage images ----
__global__ void pack_weights(const float* __restrict__ Wq, const float* __restrict__ Wk,
                             const float* __restrict__ Wv, const float* __restrict__ Wo) {
    int idx = blockIdx.x * TPB + threadIdx.x;   // 0 .. 524287
    int c   = idx & 63;
    int r   = (idx >> 6) & 127;
    int st  = idx >> 13;                        // 0..63
    int kh  = st & 1, mat = (st >> 1) & 3, hh = st >> 3;
    int kofs = kh * 64;
    float v;
    if      (mat == 0) v = Wq[(hh * 128 + r) * 128 + kofs + c];
    else if (mat == 1) v = Wk[(hh * 128 + r) * 128 + kofs + c];
    else if (mat == 2) v = Wv[(hh * 128 + r) * 128 + kofs + c];
    else               v = Wo[r * 1024 + hh * 128 + kofs + c];
    __nv_bfloat16 h = __float2bfloat16(v);
    size_t base = (size_t)st * STG_E + r * LDV + c;
    g_wpk[base]       = h;
    g_wpk[base + PSS] = __float2bfloat16(v - __bfloat162float(h));
}

__global__ __launch_bounds__(TPB, 1)
void win_msa_mma(const float* __restrict__ x,
                 const float* __restrict__ bq, const float* __restrict__ bk,
                 const float* __restrict__ bv, const float* __restrict__ bo,
                 const float* __restrict__ pos, float* __restrict__ out) {
    extern __shared__ char smraw[];
    Smem& sm = *reinterpret_cast<Smem*>(smraw);

    const int tid  = threadIdx.x, lane = tid & 31, w = tid >> 5;
    const int n    = blockIdx.x >> 8, win = blockIdx.x & 255;
    const int wy   = win >> 4, wx = win & 15;
    const int mq   = (w & 3) * 16;   // m0 for M=64 gemms (token rows)
    const int nq   = (w >> 2) * 64;  // n0 for N=128 gemms
    const int nS   = (w >> 2) * 32;  // n0 for score gemm
    const int mv   = w * 16;         // m0 for V gemm (d rows)
    const int g    = lane >> 2, tc = (lane & 3) * 2;
    const float scale = 0.088388347648318447f;  // 1/sqrt(128)

    __nv_bfloat16* b0 = sm.ws;
    __nv_bfloat16* b1 = sm.ws + STG_E;
    __nv_bfloat16* wT = b1;          // softmax weights alias stage buffer 1

    // kick off first weight stage immediately
    prefetch_stage(b0, 0, tid);

    if (tid < 64) {
        int pr = tid / 7, pc = tid % 7;
        sm.pidx[tid] = (tid < 49) ? ((wy * 7 + pr) * CW + wx * 7 + pc) : 0;
    }
    for (int f = tid; f < 4096; f += TPB) {
        int i = f >> 6, j = f & 63, vv = 0;
        if (i < 49 && j < 49)
            vv = (i / 7 - j / 7 + 6) + (i % 7 - j % 7 + 6) * 13;
        sm.rel[f] = (unsigned char)vv;
    }
    __syncthreads();

    // ---- load x window transposed: xT[tok][d], rows 49..63 zero ----
    const float* xb = x + (size_t)n * 128 * NPATCH;
    for (int f = tid; f < 8192; f += TPB) {
        int tok = f & 63, d = f >> 6;
        float vv = (tok < 49) ? xb[d * NPATCH + sm.pidx[tok]] : 0.f;
        sstore(sm.xT + tok * LDX + d, PSX, vv);
    }

    // ---- persistent O accumulator fragments (out^T[j][o]), init with bo ----
    float oacc[8][4];
    #pragma unroll
    for (int t = 0; t < 8; ++t) {
        int col = nq + t * 8 + tc;
        oacc[t][0] = bo[col];     oacc[t][1] = bo[col + 1];
        oacc[t][2] = bo[col];     oacc[t][3] = bo[col + 1];
    }
    __syncthreads();   // x stores visible

    for (int hh = 0; hh < 8; ++hh) {
        const int s = hh * 8;                      // stage base: Q0,Q1,K0,K1,V0,V1,O0,O1
        if (tid < 169) sm.bias[tid] = pos[tid * 8 + hh];

        // ================= Q^T = xT @ Wq^T =================================
        float cq[8][4];
        #pragma unroll
        for (int t = 0; t < 8; ++t) cq[t][0] = cq[t][1] = cq[t][2] = cq[t][3] = 0.f;
        prefetch_stage(b1, s + 1, tid);            // Wq k1
        CPWAIT1; __syncthreads();                  // Wq k0 ready
        wgemm<8, 4>(sm.xT + mq * LDX, LDX, PSX, b0 + nq * LDV, LDV, PSS, cq, lane);
        __syncthreads();
        prefetch_stage(b0, s + 2, tid);            // Wk k0
        CPWAIT1; __syncthreads();                  // Wq k1 ready
        wgemm<8, 4>(sm.xT + mq * LDX + 64, LDX, PSX, b1 + nq * LDV, LDV, PSS, cq, lane);
        {
            const float* bqh = bq + hh * 128;
            #pragma unroll
            for (int t = 0; t < 8; ++t) {
                int col = nq + t * 8 + tc, r0 = mq + g, r1 = r0 + 8;
                sstore2(sm.qT + r0 * LDX + col, PSX,
                        (cq[t][0] + bqh[col]) * scale, (cq[t][1] + bqh[col + 1]) * scale);
                sstore2(sm.qT + r1 * LDX + col, PSX,
                        (cq[t][2] + bqh[col]) * scale, (cq[t][3] + bqh[col + 1]) * scale);
            }
        }
        __syncthreads();

        // ================= K^T = xT @ Wk^T =================================
        float ck[8][4];
        #pragma unroll
        for (int t = 0; t < 8; ++t) ck[t][0] = ck[t][1] = ck[t][2] = ck[t][3] = 0.f;
        prefetch_stage(b1, s + 3, tid);            // Wk k1
        CPWAIT1; __syncthreads();                  // Wk k0 ready
        wgemm<8, 4>(sm.xT + mq * LDX, LDX, PSX, b0 + nq * LDV, LDV, PSS, ck, lane);
        __syncthreads();
        prefetch_stage(b0, s + 4, tid);            // Wv k0
        CPWAIT1; __syncthreads();                  // Wk k1 ready
        wgemm<8, 4>(sm.xT + mq * LDX + 64, LDX, PSX, b1 + nq * LDV, LDV, PSS, ck, lane);
        {
            const float* bkh = bk + hh * 128;
            #pragma unroll
            for (int t = 0; t < 8; ++t) {
                int col = nq + t * 8 + tc, r0 = mq + g, r1 = r0 + 8;
                sstore2(sm.kT + r0 * LDX + col, PSX,
                        ck[t][0] + bkh[col], ck[t][1] + bkh[col + 1]);
                sstore2(sm.kT + r1 * LDX + col, PSX,
                        ck[t][2] + bkh[col], ck[t][3] + bkh[col + 1]);
            }
        }
        __syncthreads();

        // ================= V = Wv @ x  (M=128 d, N=64 tok) =================
        float cv[8][4];
        #pragma unroll
        for (int t = 0; t < 8; ++t) cv[t][0] = cv[t][1] = cv[t][2] = cv[t][3] = 0.f;
        prefetch_stage(b1, s + 5, tid);            // Wv k1
        CPWAIT1; __syncthreads();                  // Wv k0 ready
        wgemm<8, 4>(b0 + mv * LDV, LDV, PSS, sm.xT, LDX, PSX, cv, lane);
        __syncthreads();
        prefetch_stage(b0, s + 6, tid);            // Wo k0
        CPWAIT1; __syncthreads();                  // Wv k1 ready
        wgemm<8, 4>(b1 + mv * LDV, LDV, PSS, sm.xT + 64, LDX, PSX, cv, lane);
        {
            const float* bvh = bv + hh * 128;
            #pragma unroll
            for (int t = 0; t < 8; ++t) {
                int tok = t * 8 + tc;
                int d0 = mv + g, d1 = d0 + 8;
                sstore2(sm.v + d0 * LDV + tok, PSV,
                        cv[t][0] + bvh[d0], cv[t][1] + bvh[d0]);
                sstore2(sm.v + d1 * LDV + tok, PSV,
                        cv[t][2] + bvh[d1], cv[t][3] + bvh[d1]);
            }
        }
        __syncthreads();   // qT, kT, v complete (b1 reads also done)

        // ================= S^T[j][i] = qT @ kT^T ===========================
        float cs[4][4];
        #pragma unroll
        for (int t = 0; t < 4; ++t) cs[t][0] = cs[t][1] = cs[t][2] = cs[t][3] = 0.f;
        wgemm<4, 8>(sm.qT + mq * LDX, LDX, PSX, sm.kT + nS * LDX, LDX, PSX, cs, lane);
        __syncthreads();   // all S reads of kT done (scores alias kT)

        float* stf = reinterpret_cast<float*>(sm.kT);
        #pragma unroll
        for (int t = 0; t < 4; ++t) {
            int i = nS + t * 8 + tc, j0 = mq + g, j1 = j0 + 8;
            stf[j0 * LDF + i]     = cs[t][0] + sm.bias[sm.rel[(i << 6) + j0]];
            stf[j0 * LDF + i + 1] = cs[t][1] + sm.bias[sm.rel[((i + 1) << 6) + j0]];
            stf[j1 * LDF + i]     = cs[t][2] + sm.bias[sm.rel[(i << 6) + j1]];
            stf[j1 * LDF + i + 1] = cs[t][3] + sm.bias[sm.rel[((i + 1) << 6) + j1]];
        }
        __syncthreads();

        // ================= softmax over i (4 threads per row j) ============
        {
            const int j = tid >> 2, p = tid & 3;
            const float* row = stf + j * LDF;
            const int i0 = p * 13;
            float m = -1e30f;
            #pragma unroll
            for (int t = 0; t < 13; ++t) {
                int i = i0 + t;
                if (i < 49) m = fmaxf(m, row[i]);
            }
            m = fmaxf(m, __shfl_xor_sync(0xffffffffu, m, 1));
            m = fmaxf(m, __shfl_xor_sync(0xffffffffu, m, 2));
            float ev[13];
            float ssum = 0.f;
            #pragma unroll
            for (int t = 0; t < 13; ++t) {
                int i = i0 + t;
                float e = (i < 49) ? __expf(row[i] - m) : 0.f;
                ev[t] = e;
                ssum += e;
            }
            ssum += __shfl_xor_sync(0xffffffffu, ssum, 1);
            ssum += __shfl_xor_sync(0xffffffffu, ssum, 2);
            float r = 1.f / ssum;
            __nv_bfloat16* wrow = wT + j * LDV;
            #pragma unroll
            for (int t = 0; t < 13; ++t) {
                int i = i0 + t;
                if (i < 49) sstore(wrow + i, PSW, ev[t] * r);
            }
            if (p == 3) {
                __nv_bfloat16 z = __float2bfloat16(0.f);
                for (int i = 49; i < 64; ++i) { wrow[i] = z; wrow[i + PSW] = z; }
            }
        }
        __syncthreads();

        // ================= oh^T = wT @ v^T (K=64) ==========================
        float ca[8][4];
        #pragma unroll
        for (int t = 0; t < 8; ++t) ca[t][0] = ca[t][1] = ca[t][2] = ca[t][3] = 0.f;
        wgemm<8, 4>(wT + mq * LDV, LDV, PSW, sm.v + nq * LDV, LDV, PSV, ca, lane);
        {   // epilogue -> ohT (aliased over qT)
            #pragma unroll
            for (int t = 0; t < 8; ++t) {
                int col = nq + t * 8 + tc, r0 = mq + g, r1 = r0 + 8;
                sstore2(sm.qT + r0 * LDX + col, PSX, ca[t][0], ca[t][1]);
                sstore2(sm.qT + r1 * LDX + col, PSX, ca[t][2], ca[t][3]);
            }
        }
        __syncthreads();   // AV done: wT (b1) dead, ohT visible

        // ================= out^T += ohT @ WoSlice^T ========================
        prefetch_stage(b1, s + 7, tid);            // Wo k1 (overwrites wT)
        CPWAIT1; __syncthreads();                  // Wo k0 ready
        wgemm<8, 4>(sm.qT + mq * LDX, LDX, PSX, b0 + nq * LDV, LDV, PSS, oacc, lane);
        __syncthreads();
        prefetch_stage(b0, (s + 8) & 63, tid);     // next head Wq k0
        CPWAIT1; __syncthreads();                  // Wo k1 ready
        wgemm<8, 4>(sm.qT + mq * LDX + 64, LDX, PSX, b1 + nq * LDV, LDV, PSS, oacc, lane);
        __syncthreads();                           // b1 reads done before reuse
    }
    CPWAIT0;

    // ---- final store: outT[j][o] -> out[n][o][patch] ----
    float* ob = out + (size_t)n * 128 * NPATCH;
    const int j0 = mq + g, j1 = j0 + 8;
    #pragma unroll
    for (int t = 0; t < 8; ++t) {
        int col = nq + t * 8 + tc;
        if (j0 < 49) {
            int p = sm.pidx[j0];
            ob[(size_t)col * NPATCH + p]       = oacc[t][0];
            ob[(size_t)(col + 1) * NPATCH + p] = oacc[t][1];
        }
        if (j1 < 49) {
            int p = sm.pidx[j1];
            ob[(size_t)col * NPATCH + p]       = oacc[t][2];
            ob[(size_t)(col + 1) * NPATCH + p] = oacc[t][3];
        }
    }
}

extern "C" void kernel_launch(void* const* d_in, const int* in_sizes, int n_in,
                              void* d_out, int out_size) {
    (void)in_sizes; (void)n_in; (void)out_size;
    const float* x   = (const float*)d_in[0];
    const float* Wq  = (const float*)d_in[1];
    const float* bq  = (const float*)d_in[2];
    const float* Wk  = (const float*)d_in[3];
    const float* bk  = (const float*)d_in[4];
    const float* Wv  = (const float*)d_in[5];
    const float* bv  = (const float*)d_in[6];
    const float* Wo  = (const float*)d_in[7];
    const float* bo  = (const float*)d_in[8];
    const float* pos = (const float*)d_in[9];
    float* out = (float*)d_out;

    pack_weights<<<2048, TPB>>>(Wq, Wk, Wv, Wo);

    const int smem_bytes = (int)sizeof(Smem);
    cudaFuncSetAttribute(win_msa_mma,
                         cudaFuncAttributeMaxDynamicSharedMemorySize, smem_bytes);
    win_msa_mma<<<1024, TPB, smem_bytes>>>(x, bq, bk, bv, bo, pos, out);
}